// round 13
// baseline (speedup 1.0000x reference)
#include <cuda_runtime.h>
#include <cuda_bf16.h>
#include <cstdint>
#include <math.h>

// Problem constants
#define B_  32
#define N_  512
#define H_  1024
#define E_  2048
#define S_  128
#define R_  (B_ * N_)          // 16384 rows
#define UVW (2 * E_ + S_)      // 4224
#define MAXSEQ 512

// ---------------- scratch (device globals; no allocations allowed) ----------
// All GEMM operands are stored pre-split as bf16 (hi, lo) pairs.
__device__ __align__(16) __nv_bfloat16 g_xh[R_ * H_], g_xl[R_ * H_];       // LN out
__device__ __align__(16) __nv_bfloat16 g_wuh[H_ * UVW], g_wul[H_ * UVW];   // uv_w
__device__ __align__(16) __nv_bfloat16 g_woh[E_ * H_], g_wol[E_ * H_];     // o_w
__device__ __align__(16) float         g_u[R_ * E_];                       // gate (fp32)
__device__ __align__(16) __nv_bfloat16 g_vh[R_ * E_], g_vl[R_ * E_];       // v
__device__ __align__(16) float         g_base[R_ * S_];                    // pre-RoPE base
__device__ __align__(16) __nv_bfloat16 g_kerh[B_ * N_ * N_], g_kerl[B_ * N_ * N_];
__device__ __align__(16) __nv_bfloat16 g_ah[R_ * E_], g_al[R_ * E_];       // gated attn
__device__ float g_sin[N_ * 64];
__device__ float g_cos[N_ * 64];

// ---------------- smem stage layout (bytes), K-chunk = 32 (R6 optimum) -------
#define A_STRIDE 80            // 40 halfs per row (128 rows x 32 k), conflict-free
#define BSTRIDE_NC 272         // 136 halfs per k-row (32 k x 128 n), conflict-free
#define OFF_AL 10240
#define OFF_BH 20480
#define OFF_BL 30720
#define STAGE  40960
#define NSTG   4
#define SMEMB  (NSTG * STAGE)  // 160 KB

// ============================ PTX helpers ====================================
__device__ __forceinline__ uint32_t smem_u32(const void* p) {
    uint32_t a;
    asm("{ .reg .u64 t; cvta.to.shared.u64 t, %1; cvt.u32.u64 %0, t; }"
        : "=r"(a) : "l"(p));
    return a;
}
__device__ __forceinline__ void cpa16(uint32_t dst, const void* src) {
    asm volatile("cp.async.cg.shared.global [%0], [%1], 16;"
                 :: "r"(dst), "l"(src) : "memory");
}
#define CP_COMMIT() asm volatile("cp.async.commit_group;" ::: "memory")
#define CP_WAIT2()  asm volatile("cp.async.wait_group 2;" ::: "memory")
#define CP_WAIT1()  asm volatile("cp.async.wait_group 1;" ::: "memory")
#define CP_WAIT0()  asm volatile("cp.async.wait_group 0;" ::: "memory")

__device__ __forceinline__ void ldm4(uint32_t r[4], uint32_t a) {
    asm volatile("ldmatrix.sync.aligned.m8n8.x4.shared.b16 {%0,%1,%2,%3}, [%4];"
        : "=r"(r[0]), "=r"(r[1]), "=r"(r[2]), "=r"(r[3]) : "r"(a));
}
__device__ __forceinline__ void ldm4t(uint32_t r[4], uint32_t a) {
    asm volatile("ldmatrix.sync.aligned.m8n8.x4.trans.shared.b16 {%0,%1,%2,%3}, [%4];"
        : "=r"(r[0]), "=r"(r[1]), "=r"(r[2]), "=r"(r[3]) : "r"(a));
}
__device__ __forceinline__ void mma16816(float d[4], const uint32_t a[4],
                                         const uint32_t b[2]) {
    asm volatile(
        "mma.sync.aligned.m16n8k16.row.col.f32.bf16.bf16.f32 "
        "{%0,%1,%2,%3}, {%4,%5,%6,%7}, {%8,%9}, {%0,%1,%2,%3};"
        : "+f"(d[0]), "+f"(d[1]), "+f"(d[2]), "+f"(d[3])
        : "r"(a[0]), "r"(a[1]), "r"(a[2]), "r"(a[3]), "r"(b[0]), "r"(b[1]));
}

// ---------------- bf16 hi/lo split -------------------------------------------
__device__ __forceinline__ void split2(float a, float b, uint32_t& hi, uint32_t& lo) {
    __nv_bfloat16 ah = __float2bfloat16(a), bh = __float2bfloat16(b);
    __nv_bfloat16 al = __float2bfloat16(a - __bfloat162float(ah));
    __nv_bfloat16 bl = __float2bfloat16(b - __bfloat162float(bh));
    __nv_bfloat162 h; h.x = ah; h.y = bh;
    __nv_bfloat162 l; l.x = al; l.y = bl;
    hi = *reinterpret_cast<uint32_t*>(&h);
    lo = *reinterpret_cast<uint32_t*>(&l);
}

// ---------------- generic bf16x3 mma.sync GEMM with fused epilogues ----------
// 128x128 CTA tile, 512 threads, 16 warps (4x4 grid) of 32x32 warp tiles.
// K-chunk 32, 4-stage cp.async pipeline with exact tail-safe waits.
// BNC: B operand is N-contiguous [K,N] (else K-contiguous [N,K])
// EPI: 0 = uv (bias+silu -> u | vh/vl | base), 1 = scores (FUSED RoPE prologue,
//      -> kerh/kerl), 2 = attn (*u -> ah/al), 3 = out (+o_b + residual -> C)
template <int BNC, int EPI>
__global__ __launch_bounds__(512, 1)
void gau_gemm(const __nv_bfloat16* __restrict__ Ah, const __nv_bfloat16* __restrict__ Al,
              int lda, long long sAz,
              const __nv_bfloat16* __restrict__ Bh, const __nv_bfloat16* __restrict__ Bl,
              int ldb, long long sBz,
              int K,
              const float* __restrict__ e0, const float* __restrict__ e1,
              const float* __restrict__ gmv, const float* __restrict__ btv,
              const float* __restrict__ basep,
              float* __restrict__ C)
{
    extern __shared__ char sm[];
    const int tid = threadIdx.x, wid = tid >> 5, lane = tid & 31;
    const int z = blockIdx.z;

    const uint32_t sbase = smem_u32(sm);
    const int mb = (wid & 3) * 32;
    const int nb = (wid >> 2) * 32;
    const int nch = K / 32;

    if (EPI == 1) {
        // ---- fused RoPE prologue: build q (A) / k (B) tiles in all 4 stages ----
        const int r = tid >> 2;            // 0..127
        const int s4 = tid & 3;            // stage == 32-col block
        const int j0 = s4 * 32;
        #pragma unroll
        for (int qk = 0; qk < 2; ++qk) {
            int rloc = (qk == 0 ? (int)blockIdx.y : (int)blockIdx.x) * 128 + r; // 0..511
            const float* brow = basep + ((size_t)z * N_ + rloc) * S_;
            const float* gm = gmv + qk * 128;
            const float* bt = btv + qk * 128;
            char* dst = sm + s4 * STAGE + r * A_STRIDE + (qk ? OFF_BH : 0);
            #pragma unroll
            for (int jj = 0; jj < 32; jj += 2) {
                int j = j0 + jj;
                float v0, v1;
                if (j < 64) {
                    float sn0 = g_sin[rloc * 64 + j],     cs0 = g_cos[rloc * 64 + j];
                    float sn1 = g_sin[rloc * 64 + j + 1], cs1 = g_cos[rloc * 64 + j + 1];
                    float p1a = brow[j]      * gm[j]      + bt[j];
                    float p2a = brow[j + 64] * gm[j + 64] + bt[j + 64];
                    float p1b = brow[j + 1]  * gm[j + 1]  + bt[j + 1];
                    float p2b = brow[j + 65] * gm[j + 65] + bt[j + 65];
                    v0 = p1a * cs0 - p2a * sn0;
                    v1 = p1b * cs1 - p2b * sn1;
                } else {
                    int d = j - 64;
                    float sn0 = g_sin[rloc * 64 + d],     cs0 = g_cos[rloc * 64 + d];
                    float sn1 = g_sin[rloc * 64 + d + 1], cs1 = g_cos[rloc * 64 + d + 1];
                    float p1a = brow[d]     * gm[d]     + bt[d];
                    float p2a = brow[j]     * gm[j]     + bt[j];
                    float p1b = brow[d + 1] * gm[d + 1] + bt[d + 1];
                    float p2b = brow[j + 1] * gm[j + 1] + bt[j + 1];
                    v0 = p2a * cs0 + p1a * sn0;
                    v1 = p2b * cs1 + p1b * sn1;
                }
                uint32_t h, l; split2(v0, v1, h, l);
                *(uint32_t*)(dst + jj * 2) = h;
                *(uint32_t*)(dst + OFF_AL + jj * 2) = l;
            }
        }
        __syncthreads();
    } else {
        Ah += (size_t)z * sAz + (size_t)blockIdx.y * 128 * lda;
        Al += (size_t)z * sAz + (size_t)blockIdx.y * 128 * lda;
        if (BNC) { Bh += (size_t)z * sBz + blockIdx.x * 128;
                   Bl += (size_t)z * sBz + blockIdx.x * 128; }
        else     { Bh += (size_t)z * sBz + (size_t)blockIdx.x * 128 * ldb;
                   Bl += (size_t)z * sBz + (size_t)blockIdx.x * 128 * ldb; }
    }

    // cp.async thread mappings
    const int ar = tid >> 2, ag = tid & 3;     // kc: row 0..127, 16B granule
    const int bk = tid >> 4, bg = tid & 15;    // nc: k-row 0..31, 16B granule

    float acc[2][4][4];
    #pragma unroll
    for (int i = 0; i < 2; ++i)
        #pragma unroll
        for (int j = 0; j < 4; ++j)
            #pragma unroll
            for (int q = 0; q < 4; ++q) acc[i][j][q] = 0.f;

    auto issue = [&](int c) {
        uint32_t sb = sbase + (c & (NSTG - 1)) * STAGE;
        uint32_t da = sb + ar * A_STRIDE + ag * 16;
        cpa16(da,          Ah + (size_t)ar * lda + c * 32 + ag * 8);
        cpa16(da + OFF_AL, Al + (size_t)ar * lda + c * 32 + ag * 8);
        if (BNC) {
            uint32_t db = sb + OFF_BH + bk * BSTRIDE_NC + bg * 16;
            cpa16(db,                     Bh + (size_t)(c * 32 + bk) * ldb + bg * 8);
            cpa16(db + (OFF_BL - OFF_BH), Bl + (size_t)(c * 32 + bk) * ldb + bg * 8);
        } else {
            uint32_t db = sb + OFF_BH + ar * A_STRIDE + ag * 16;
            cpa16(db,                     Bh + (size_t)ar * ldb + c * 32 + ag * 8);
            cpa16(db + (OFF_BL - OFF_BH), Bl + (size_t)ar * ldb + c * 32 + ag * 8);
        }
        CP_COMMIT();
    };

    if (EPI != 1) {
        issue(0);
        if (nch > 1) issue(1);
        if (nch > 2) issue(2);
    }

    for (int c = 0; c < nch; ++c) {
        if (EPI != 1) {
            // groups issued = min(c+3, nch); need group c done -> allow issued-c-1
            if (c + 3 <= nch) CP_WAIT2();
            else if (c + 2 == nch) CP_WAIT1();
            else CP_WAIT0();
            __syncthreads();                 // data visible + prev compute done
            if (c + 3 < nch) issue(c + 3);   // overwrites stage (c-1)%4: safe
        }

        uint32_t sb = sbase + (c & (NSTG - 1)) * STAGE;
        #pragma unroll
        for (int ks = 0; ks < 2; ++ks) {
            uint32_t ah[2][4], al[2][4];
            #pragma unroll
            for (int mt = 0; mt < 2; ++mt) {
                uint32_t ad = sb + (mb + mt * 16 + (lane & 15)) * A_STRIDE
                            + ks * 32 + (lane >> 4) * 16;
                ldm4(ah[mt], ad);
                ldm4(al[mt], ad + OFF_AL);
            }
            uint32_t bh[4][2], bl[4][2];
            #pragma unroll
            for (int np = 0; np < 2; ++np) {     // each x4 covers two n8 groups
                uint32_t r[4];
                if (BNC) {
                    uint32_t bd = sb + OFF_BH
                                + (ks * 16 + (lane & 15)) * BSTRIDE_NC
                                + (nb + np * 16 + (lane >> 4) * 8) * 2;
                    ldm4t(r, bd);
                    bh[np*2][0]=r[0]; bh[np*2][1]=r[1]; bh[np*2+1][0]=r[2]; bh[np*2+1][1]=r[3];
                    ldm4t(r, bd + (OFF_BL - OFF_BH));
                    bl[np*2][0]=r[0]; bl[np*2][1]=r[1]; bl[np*2+1][0]=r[2]; bl[np*2+1][1]=r[3];
                } else {
                    uint32_t bd = sb + OFF_BH
                                + (nb + np * 16 + (lane >> 4) * 8 + (lane & 7)) * A_STRIDE
                                + ks * 32 + ((lane >> 3) & 1) * 16;
                    ldm4(r, bd);
                    bh[np*2][0]=r[0]; bh[np*2][1]=r[1]; bh[np*2+1][0]=r[2]; bh[np*2+1][1]=r[3];
                    ldm4(r, bd + (OFF_BL - OFF_BH));
                    bl[np*2][0]=r[0]; bl[np*2][1]=r[1]; bl[np*2+1][0]=r[2]; bl[np*2+1][1]=r[3];
                }
            }
            #pragma unroll
            for (int mt = 0; mt < 2; ++mt)
                #pragma unroll
                for (int nt = 0; nt < 4; ++nt) {
                    mma16816(acc[mt][nt], ah[mt], bh[nt]);
                    mma16816(acc[mt][nt], ah[mt], bl[nt]);
                    mma16816(acc[mt][nt], al[mt], bh[nt]);
                }
        }
    }

    // ---------------- fused epilogue straight from fragments ----------------
    const int rbase = blockIdx.y * 128 + mb + (lane >> 2);
    const int cbase = blockIdx.x * 128 + nb + (lane & 3) * 2;
    const int xb = blockIdx.x;
    #pragma unroll
    for (int mt = 0; mt < 2; ++mt) {
        #pragma unroll
        for (int hf = 0; hf < 2; ++hf) {
            int r = rbase + mt * 16 + hf * 8;
            int grow = z * N_ + r;                  // global row (z=0 when unbatched)
            #pragma unroll
            for (int nt = 0; nt < 4; ++nt) {
                float v0 = acc[mt][nt][hf * 2 + 0];
                float v1 = acc[mt][nt][hf * 2 + 1];
                int cc = cbase + nt * 8;
                if (EPI == 0) {
                    v0 += e0[cc];     v1 += e0[cc + 1];
                    v0 = v0 / (1.f + expf(-v0));
                    v1 = v1 / (1.f + expf(-v1));
                    if (xb < 16) {
                        *(float2*)&g_u[(size_t)grow * E_ + cc] = make_float2(v0, v1);
                    } else if (xb < 32) {
                        uint32_t h, l; split2(v0, v1, h, l);
                        size_t idx = (size_t)grow * E_ + (cc - E_);
                        *(uint32_t*)&g_vh[idx] = h;
                        *(uint32_t*)&g_vl[idx] = l;
                    } else {
                        *(float2*)&g_base[(size_t)grow * S_ + (cc - 2 * E_)] =
                            make_float2(v0, v1);
                    }
                } else if (EPI == 1) {
                    float m0 = (1.f - e1[z * N_ + cc])     * (-1e12f);
                    float m1 = (1.f - e1[z * N_ + cc + 1]) * (-1e12f);
                    float s0 = v0 * (1.f / MAXSEQ) + e0[cc - r + (MAXSEQ - 1)]     + m0;
                    float s1 = v1 * (1.f / MAXSEQ) + e0[cc + 1 - r + (MAXSEQ - 1)] + m1;
                    s0 = fmaxf(s0, 0.f); s1 = fmaxf(s1, 0.f);
                    uint32_t h, l; split2(s0 * s0, s1 * s1, h, l);
                    size_t idx = ((size_t)z * N_ + r) * N_ + cc;
                    *(uint32_t*)&g_kerh[idx] = h;
                    *(uint32_t*)&g_kerl[idx] = l;
                } else if (EPI == 2) {
                    float2 u = *(const float2*)&g_u[(size_t)grow * E_ + cc];
                    uint32_t h, l; split2(v0 * u.x, v1 * u.y, h, l);
                    size_t idx = (size_t)grow * E_ + cc;
                    *(uint32_t*)&g_ah[idx] = h;
                    *(uint32_t*)&g_al[idx] = l;
                } else {
                    float2 xr = *(const float2*)&e1[(size_t)grow * H_ + cc];
                    *(float2*)&C[(size_t)grow * H_ + cc] =
                        make_float2(v0 + e0[cc] + xr.x, v1 + e0[cc + 1] + xr.y);
                }
            }
        }
    }
}

// ---------------- one-time fp32 -> bf16 hi/lo weight split -------------------
__global__ void split_kernel(const float* __restrict__ src,
                             __nv_bfloat16* __restrict__ h,
                             __nv_bfloat16* __restrict__ l, int n2) {
    int i = blockIdx.x * 256 + threadIdx.x;
    if (i >= n2) return;
    float2 v = ((const float2*)src)[i];
    uint32_t hi, lo; split2(v.x, v.y, hi, lo);
    ((uint32_t*)h)[i] = hi;
    ((uint32_t*)l)[i] = lo;
}

// ---------------- sin/cos table (replicates reference fp32 arithmetic) ------
__global__ void sincos_kernel() {
    int i = blockIdx.x * 256 + threadIdx.x;
    if (i >= N_ * 64) return;
    int d = i & 63;
    int pos = i >> 6;
    float invf = (float)pow(10000.0, (double)d * (1.0 / 64.0));
    float arg = (float)pos * invf;
    g_sin[i] = (float)sin((double)arg);
    g_cos[i] = (float)cos((double)arg);
}

// ---------------- LayerNorm -> split bf16 ------------------------------------
__global__ __launch_bounds__(256) void ln_kernel(
    const float* __restrict__ x, const float* __restrict__ ln_g,
    const float* __restrict__ ln_b)
{
    int row = blockIdx.x;
    const float4* xr = (const float4*)(x + (size_t)row * H_);
    float4 v = xr[threadIdx.x];
    float s = v.x + v.y + v.z + v.w;
    float sq = v.x * v.x + v.y * v.y + v.z * v.z + v.w * v.w;
    #pragma unroll
    for (int o = 16; o; o >>= 1) {
        s  += __shfl_down_sync(0xffffffffu, s, o);
        sq += __shfl_down_sync(0xffffffffu, sq, o);
    }
    __shared__ float ss[8], ssq[8];
    int wrp = threadIdx.x >> 5, l = threadIdx.x & 31;
    if (l == 0) { ss[wrp] = s; ssq[wrp] = sq; }
    __syncthreads();
    if (wrp == 0) {
        s  = (l < 8) ? ss[l] : 0.f;
        sq = (l < 8) ? ssq[l] : 0.f;
        #pragma unroll
        for (int o = 4; o; o >>= 1) {
            s  += __shfl_down_sync(0xffu, s, o);
            sq += __shfl_down_sync(0xffu, sq, o);
        }
        if (l == 0) { ss[0] = s; ssq[0] = sq; }
    }
    __syncthreads();
    float mu = ss[0] * (1.f / H_);
    float var = ssq[0] * (1.f / H_) - mu * mu;
    float rs = rsqrtf(var + 1e-5f);
    float4 g = ((const float4*)ln_g)[threadIdx.x];
    float4 bb = ((const float4*)ln_b)[threadIdx.x];
    float o0 = (v.x - mu) * rs * g.x + bb.x;
    float o1 = (v.y - mu) * rs * g.y + bb.y;
    float o2 = (v.z - mu) * rs * g.z + bb.z;
    float o3 = (v.w - mu) * rs * g.w + bb.w;
    uint32_t h0, l0, h1, l1;
    split2(o0, o1, h0, l0);
    split2(o2, o3, h1, l1);
    int idx = row * (H_ / 4) + threadIdx.x;        // uint2 = 4 bf16
    ((uint2*)g_xh)[idx] = make_uint2(h0, h1);
    ((uint2*)g_xl)[idx] = make_uint2(l0, l1);
}

// ---------------- launch -----------------------------------------------------
extern "C" void kernel_launch(void* const* d_in, const int* in_sizes, int n_in,
                              void* d_out, int out_size)
{
    const float* x     = (const float*)d_in[0];
    const float* mask  = (const float*)d_in[1];
    const float* gamma = (const float*)d_in[2];
    const float* beta  = (const float*)d_in[3];
    const float* w     = (const float*)d_in[4];
    const float* uv_w  = (const float*)d_in[7];
    const float* uv_b  = (const float*)d_in[8];
    const float* o_w   = (const float*)d_in[9];
    const float* o_b   = (const float*)d_in[10];
    const float* ln_g  = (const float*)d_in[11];
    const float* ln_b  = (const float*)d_in[12];
    float* out = (float*)d_out;

    cudaFuncSetAttribute(gau_gemm<1, 0>, cudaFuncAttributeMaxDynamicSharedMemorySize, SMEMB);
    cudaFuncSetAttribute(gau_gemm<0, 1>, cudaFuncAttributeMaxDynamicSharedMemorySize, SMEMB);
    cudaFuncSetAttribute(gau_gemm<1, 2>, cudaFuncAttributeMaxDynamicSharedMemorySize, SMEMB);
    cudaFuncSetAttribute(gau_gemm<1, 3>, cudaFuncAttributeMaxDynamicSharedMemorySize, SMEMB);

    __nv_bfloat16 *p_xh, *p_xl, *p_wuh, *p_wul, *p_woh, *p_wol;
    __nv_bfloat16 *p_vh, *p_vl, *p_kerh, *p_kerl, *p_ahh, *p_all;
    float *p_base;
    cudaGetSymbolAddress((void**)&p_xh,  g_xh);  cudaGetSymbolAddress((void**)&p_xl,  g_xl);
    cudaGetSymbolAddress((void**)&p_wuh, g_wuh); cudaGetSymbolAddress((void**)&p_wul, g_wul);
    cudaGetSymbolAddress((void**)&p_woh, g_woh); cudaGetSymbolAddress((void**)&p_wol, g_wol);
    cudaGetSymbolAddress((void**)&p_vh,  g_vh);  cudaGetSymbolAddress((void**)&p_vl,  g_vl);
    cudaGetSymbolAddress((void**)&p_kerh,g_kerh);cudaGetSymbolAddress((void**)&p_kerl,g_kerl);
    cudaGetSymbolAddress((void**)&p_ahh, g_ah);  cudaGetSymbolAddress((void**)&p_all, g_al);
    cudaGetSymbolAddress((void**)&p_base,g_base);

    sincos_kernel<<<128, 256>>>();
    split_kernel<<<(H_ * UVW / 2 + 255) / 256, 256>>>(uv_w, p_wuh, p_wul, H_ * UVW / 2);
    split_kernel<<<(E_ * H_ / 2 + 255) / 256, 256>>>(o_w, p_woh, p_wol, E_ * H_ / 2);
    ln_kernel<<<R_, 256>>>(x, ln_g, ln_b);

    // uv = silu(xn @ uv_w + uv_b)        [16384 x 4224 x 1024], B n-contig
    gau_gemm<1, 0><<<dim3(UVW / 128, R_ / 128, 1), 512, SMEMB>>>(
        p_xh, p_xl, H_, 0LL, p_wuh, p_wul, UVW, 0LL, H_,
        uv_b, nullptr, nullptr, nullptr, nullptr, nullptr);

    // kernel = relu(q@k^T/512 + bias + mask)^2   [512 x 512 x 128] x32
    // RoPE fused: q/k tiles built in-kernel from g_base + gamma/beta + sincos
    gau_gemm<0, 1><<<dim3(N_ / 128, N_ / 128, B_), 512, SMEMB>>>(
        nullptr, nullptr, S_, 0LL, nullptr, nullptr, S_, 0LL, S_,
        w, mask, gamma, beta, p_base, nullptr);

    // attn = u * (kernel @ v)            [512 x 2048 x 512] x32, B n-contig
    gau_gemm<1, 2><<<dim3(E_ / 128, N_ / 128, B_), 512, SMEMB>>>(
        p_kerh, p_kerl, N_, (long long)N_ * N_, p_vh, p_vl, E_, (long long)N_ * E_,
        N_, nullptr, nullptr, nullptr, nullptr, nullptr, nullptr);

    // out = attn @ o_w + o_b + x         [16384 x 1024 x 2048], B n-contig
    gau_gemm<1, 3><<<dim3(H_ / 128, R_ / 128, 1), 512, SMEMB>>>(
        p_ahh, p_all, E_, 0LL, p_woh, p_wol, H_, 0LL, E_,
        o_b, x, nullptr, nullptr, nullptr, out);
}

// round 14
// speedup vs baseline: 1.1892x; 1.1892x over previous
#include <cuda_runtime.h>
#include <cuda_bf16.h>
#include <cstdint>
#include <math.h>

// Problem constants
#define B_  32
#define N_  512
#define H_  1024
#define E_  2048
#define S_  128
#define R_  (B_ * N_)          // 16384 rows
#define UVW (2 * E_ + S_)      // 4224
#define MAXSEQ 512

// ---------------- scratch (device globals; no allocations allowed) ----------
// All GEMM operands are stored pre-split as bf16 (hi, lo) pairs.
__device__ __align__(16) __nv_bfloat16 g_xh[R_ * H_], g_xl[R_ * H_];       // LN out
__device__ __align__(16) __nv_bfloat16 g_wuh[H_ * UVW], g_wul[H_ * UVW];   // uv_w
__device__ __align__(16) __nv_bfloat16 g_woh[E_ * H_], g_wol[E_ * H_];     // o_w
__device__ __align__(16) float         g_u[R_ * E_];                       // gate (fp32)
__device__ __align__(16) __nv_bfloat16 g_vh[R_ * E_], g_vl[R_ * E_];       // v
__device__ __align__(16) float         g_base[R_ * S_];                    // pre-RoPE base
__device__ __align__(16) __nv_bfloat16 g_qh[R_ * S_], g_ql[R_ * S_];
__device__ __align__(16) __nv_bfloat16 g_kh[R_ * S_], g_kl[R_ * S_];
__device__ __align__(16) __nv_bfloat16 g_kerh[B_ * N_ * N_], g_kerl[B_ * N_ * N_];
__device__ __align__(16) __nv_bfloat16 g_ah[R_ * E_], g_al[R_ * E_];       // gated attn
__device__ float g_sin[N_ * 64];
__device__ float g_cos[N_ * 64];

// ---------------- smem stage layout (bytes), K-chunk = 32 (R6 optimum) -------
#define A_STRIDE 80            // 40 halfs per row (128 rows x 32 k), conflict-free
#define BSTRIDE_NC 272         // 136 halfs per k-row (32 k x 128 n), conflict-free
#define OFF_AL 10240
#define OFF_BH 20480
#define OFF_BL 30720
#define STAGE  40960
#define NSTG   4
#define SMEMB  (NSTG * STAGE)  // 160 KB

// ============================ PTX helpers ====================================
__device__ __forceinline__ uint32_t smem_u32(const void* p) {
    uint32_t a;
    asm("{ .reg .u64 t; cvta.to.shared.u64 t, %1; cvt.u32.u64 %0, t; }"
        : "=r"(a) : "l"(p));
    return a;
}
__device__ __forceinline__ void cpa16(uint32_t dst, const void* src) {
    asm volatile("cp.async.cg.shared.global [%0], [%1], 16;"
                 :: "r"(dst), "l"(src) : "memory");
}
#define CP_COMMIT() asm volatile("cp.async.commit_group;" ::: "memory")
template <int NW>
__device__ __forceinline__ void cp_wait() {
    asm volatile("cp.async.wait_group %0;" :: "n"(NW) : "memory");
}

__device__ __forceinline__ void ldm4(uint32_t r[4], uint32_t a) {
    asm volatile("ldmatrix.sync.aligned.m8n8.x4.shared.b16 {%0,%1,%2,%3}, [%4];"
        : "=r"(r[0]), "=r"(r[1]), "=r"(r[2]), "=r"(r[3]) : "r"(a));
}
__device__ __forceinline__ void ldm4t(uint32_t r[4], uint32_t a) {
    asm volatile("ldmatrix.sync.aligned.m8n8.x4.trans.shared.b16 {%0,%1,%2,%3}, [%4];"
        : "=r"(r[0]), "=r"(r[1]), "=r"(r[2]), "=r"(r[3]) : "r"(a));
}
__device__ __forceinline__ void mma16816(float d[4], const uint32_t a[4],
                                         const uint32_t b[2]) {
    asm volatile(
        "mma.sync.aligned.m16n8k16.row.col.f32.bf16.bf16.f32 "
        "{%0,%1,%2,%3}, {%4,%5,%6,%7}, {%8,%9}, {%0,%1,%2,%3};"
        : "+f"(d[0]), "+f"(d[1]), "+f"(d[2]), "+f"(d[3])
        : "r"(a[0]), "r"(a[1]), "r"(a[2]), "r"(a[3]), "r"(b[0]), "r"(b[1]));
}

// ---------------- bf16 hi/lo split -------------------------------------------
__device__ __forceinline__ void split2(float a, float b, uint32_t& hi, uint32_t& lo) {
    __nv_bfloat16 ah = __float2bfloat16(a), bh = __float2bfloat16(b);
    __nv_bfloat16 al = __float2bfloat16(a - __bfloat162float(ah));
    __nv_bfloat16 bl = __float2bfloat16(b - __bfloat162float(bh));
    __nv_bfloat162 h; h.x = ah; h.y = bh;
    __nv_bfloat162 l; l.x = al; l.y = bl;
    hi = *reinterpret_cast<uint32_t*>(&h);
    lo = *reinterpret_cast<uint32_t*>(&l);
}

// ---------------- generic bf16x3 mma.sync GEMM with fused epilogues ----------
// 128x128 CTA tile, 512 threads, 16 warps (4x4 grid) of 32x32 warp tiles.
// K-chunk 32, 4-stage cp.async pipeline. NCH = K/32 is compile-time: the main
// loop unrolls (stage offsets become immediates) and tail waits are exact.
// BNC: B operand is N-contiguous [K,N] (else K-contiguous [N,K])
// EPI: 0 = uv (bias+silu -> u | vh/vl | base), 1 = scores (-> kerh/kerl),
//      2 = attn (*u -> ah/al), 3 = out (+o_b + residual -> C)
template <int BNC, int EPI, int NCH>
__global__ __launch_bounds__(512, 1)
void gau_gemm(const __nv_bfloat16* __restrict__ Ah, const __nv_bfloat16* __restrict__ Al,
              int lda, long long sAz,
              const __nv_bfloat16* __restrict__ Bh, const __nv_bfloat16* __restrict__ Bl,
              int ldb, long long sBz,
              const float* __restrict__ e0, const float* __restrict__ e1,
              float* __restrict__ C)
{
    extern __shared__ char sm[];
    const int tid = threadIdx.x, wid = tid >> 5, lane = tid & 31;
    const int z = blockIdx.z;

    Ah += (size_t)z * sAz + (size_t)blockIdx.y * 128 * lda;
    Al += (size_t)z * sAz + (size_t)blockIdx.y * 128 * lda;
    if (BNC) { Bh += (size_t)z * sBz + blockIdx.x * 128;
               Bl += (size_t)z * sBz + blockIdx.x * 128; }
    else     { Bh += (size_t)z * sBz + (size_t)blockIdx.x * 128 * ldb;
               Bl += (size_t)z * sBz + (size_t)blockIdx.x * 128 * ldb; }

    const uint32_t sbase = smem_u32(sm);
    const int mb = (wid & 3) * 32;
    const int nb = (wid >> 2) * 32;

    // cp.async thread mappings (512 threads; one 16B granule per array)
    const int ar = tid >> 2, ag = tid & 3;     // kc: row 0..127, 16B granule
    const int bk = tid >> 4, bg = tid & 15;    // nc: k-row 0..31, 16B granule

    float acc[2][4][4];
    #pragma unroll
    for (int i = 0; i < 2; ++i)
        #pragma unroll
        for (int j = 0; j < 4; ++j)
            #pragma unroll
            for (int q = 0; q < 4; ++q) acc[i][j][q] = 0.f;

    auto issue = [&](int c) {
        uint32_t sb = sbase + (c & (NSTG - 1)) * STAGE;
        uint32_t da = sb + ar * A_STRIDE + ag * 16;
        cpa16(da,          Ah + (size_t)ar * lda + c * 32 + ag * 8);
        cpa16(da + OFF_AL, Al + (size_t)ar * lda + c * 32 + ag * 8);
        if (BNC) {
            uint32_t db = sb + OFF_BH + bk * BSTRIDE_NC + bg * 16;
            cpa16(db,                     Bh + (size_t)(c * 32 + bk) * ldb + bg * 8);
            cpa16(db + (OFF_BL - OFF_BH), Bl + (size_t)(c * 32 + bk) * ldb + bg * 8);
        } else {
            uint32_t db = sb + OFF_BH + ar * A_STRIDE + ag * 16;
            cpa16(db,                     Bh + (size_t)ar * ldb + c * 32 + ag * 8);
            cpa16(db + (OFF_BL - OFF_BH), Bl + (size_t)ar * ldb + c * 32 + ag * 8);
        }
        CP_COMMIT();
    };

    auto compute = [&](int c) {
        uint32_t sb = sbase + (c & (NSTG - 1)) * STAGE;
        #pragma unroll
        for (int ks = 0; ks < 2; ++ks) {
            uint32_t ah[2][4], al[2][4];
            #pragma unroll
            for (int mt = 0; mt < 2; ++mt) {
                uint32_t ad = sb + (mb + mt * 16 + (lane & 15)) * A_STRIDE
                            + ks * 32 + (lane >> 4) * 16;
                ldm4(ah[mt], ad);
                ldm4(al[mt], ad + OFF_AL);
            }
            uint32_t bh[4][2], bl[4][2];
            #pragma unroll
            for (int np = 0; np < 2; ++np) {     // each x4 covers two n8 groups
                uint32_t r[4];
                if (BNC) {
                    uint32_t bd = sb + OFF_BH
                                + (ks * 16 + (lane & 15)) * BSTRIDE_NC
                                + (nb + np * 16 + (lane >> 4) * 8) * 2;
                    ldm4t(r, bd);
                    bh[np*2][0]=r[0]; bh[np*2][1]=r[1]; bh[np*2+1][0]=r[2]; bh[np*2+1][1]=r[3];
                    ldm4t(r, bd + (OFF_BL - OFF_BH));
                    bl[np*2][0]=r[0]; bl[np*2][1]=r[1]; bl[np*2+1][0]=r[2]; bl[np*2+1][1]=r[3];
                } else {
                    uint32_t bd = sb + OFF_BH
                                + (nb + np * 16 + (lane >> 4) * 8 + (lane & 7)) * A_STRIDE
                                + ks * 32 + ((lane >> 3) & 1) * 16;
                    ldm4(r, bd);
                    bh[np*2][0]=r[0]; bh[np*2][1]=r[1]; bh[np*2+1][0]=r[2]; bh[np*2+1][1]=r[3];
                    ldm4(r, bd + (OFF_BL - OFF_BH));
                    bl[np*2][0]=r[0]; bl[np*2][1]=r[1]; bl[np*2+1][0]=r[2]; bl[np*2+1][1]=r[3];
                }
            }
            #pragma unroll
            for (int mt = 0; mt < 2; ++mt)
                #pragma unroll
                for (int nt = 0; nt < 4; ++nt) {
                    mma16816(acc[mt][nt], ah[mt], bh[nt]);
                    mma16816(acc[mt][nt], ah[mt], bl[nt]);
                    mma16816(acc[mt][nt], al[mt], bh[nt]);
                }
        }
    };

    issue(0); issue(1); issue(2);

    // main loop: exact steady-state wait (group c done once all but newest 2 drain)
    #pragma unroll 4
    for (int c = 0; c < NCH - 2; ++c) {
        cp_wait<2>();
        __syncthreads();                 // data visible + prev compute done
        if (c + 3 < NCH) issue(c + 3);   // overwrites stage (c-1)%4: safe
        compute(c);
    }
    // peeled tail: exact waits (R6's fixed wait2 here was a latent race)
    cp_wait<1>();
    __syncthreads();
    compute(NCH - 2);
    cp_wait<0>();
    __syncthreads();
    compute(NCH - 1);

    // ---------------- fused epilogue straight from fragments ----------------
    const int rbase = blockIdx.y * 128 + mb + (lane >> 2);
    const int cbase = blockIdx.x * 128 + nb + (lane & 3) * 2;
    const int xb = blockIdx.x;
    #pragma unroll
    for (int mt = 0; mt < 2; ++mt) {
        #pragma unroll
        for (int hf = 0; hf < 2; ++hf) {
            int r = rbase + mt * 16 + hf * 8;
            int grow = z * N_ + r;                  // global row (z=0 when unbatched)
            #pragma unroll
            for (int nt = 0; nt < 4; ++nt) {
                float v0 = acc[mt][nt][hf * 2 + 0];
                float v1 = acc[mt][nt][hf * 2 + 1];
                int cc = cbase + nt * 8;
                if (EPI == 0) {
                    v0 += e0[cc];     v1 += e0[cc + 1];
                    v0 = v0 / (1.f + expf(-v0));
                    v1 = v1 / (1.f + expf(-v1));
                    if (xb < 16) {
                        *(float2*)&g_u[(size_t)grow * E_ + cc] = make_float2(v0, v1);
                    } else if (xb < 32) {
                        uint32_t h, l; split2(v0, v1, h, l);
                        size_t idx = (size_t)grow * E_ + (cc - E_);
                        *(uint32_t*)&g_vh[idx] = h;
                        *(uint32_t*)&g_vl[idx] = l;
                    } else {
                        *(float2*)&g_base[(size_t)grow * S_ + (cc - 2 * E_)] =
                            make_float2(v0, v1);
                    }
                } else if (EPI == 1) {
                    float m0 = (1.f - e1[z * N_ + cc])     * (-1e12f);
                    float m1 = (1.f - e1[z * N_ + cc + 1]) * (-1e12f);
                    float s0 = v0 * (1.f / MAXSEQ) + e0[cc - r + (MAXSEQ - 1)]     + m0;
                    float s1 = v1 * (1.f / MAXSEQ) + e0[cc + 1 - r + (MAXSEQ - 1)] + m1;
                    s0 = fmaxf(s0, 0.f); s1 = fmaxf(s1, 0.f);
                    uint32_t h, l; split2(s0 * s0, s1 * s1, h, l);
                    size_t idx = ((size_t)z * N_ + r) * N_ + cc;
                    *(uint32_t*)&g_kerh[idx] = h;
                    *(uint32_t*)&g_kerl[idx] = l;
                } else if (EPI == 2) {
                    float2 u = *(const float2*)&g_u[(size_t)grow * E_ + cc];
                    uint32_t h, l; split2(v0 * u.x, v1 * u.y, h, l);
                    size_t idx = (size_t)grow * E_ + cc;
                    *(uint32_t*)&g_ah[idx] = h;
                    *(uint32_t*)&g_al[idx] = l;
                } else {
                    float2 xr = *(const float2*)&e1[(size_t)grow * H_ + cc];
                    *(float2*)&C[(size_t)grow * H_ + cc] =
                        make_float2(v0 + e0[cc] + xr.x, v1 + e0[cc + 1] + xr.y);
                }
            }
        }
    }
}

// ---------------- one-time fp32 -> bf16 hi/lo weight split -------------------
__global__ void split_kernel(const float* __restrict__ src,
                             __nv_bfloat16* __restrict__ h,
                             __nv_bfloat16* __restrict__ l, int n2) {
    int i = blockIdx.x * 256 + threadIdx.x;
    if (i >= n2) return;
    float2 v = ((const float2*)src)[i];
    uint32_t hi, lo; split2(v.x, v.y, hi, lo);
    ((uint32_t*)h)[i] = hi;
    ((uint32_t*)l)[i] = lo;
}

// ---------------- sin/cos table (replicates reference fp32 arithmetic) ------
__global__ void sincos_kernel() {
    int i = blockIdx.x * 256 + threadIdx.x;
    if (i >= N_ * 64) return;
    int d = i & 63;
    int pos = i >> 6;
    float invf = (float)pow(10000.0, (double)d * (1.0 / 64.0));
    float arg = (float)pos * invf;
    g_sin[i] = (float)sin((double)arg);
    g_cos[i] = (float)cos((double)arg);
}

// ---------------- LayerNorm -> split bf16 ------------------------------------
__global__ __launch_bounds__(256) void ln_kernel(
    const float* __restrict__ x, const float* __restrict__ ln_g,
    const float* __restrict__ ln_b)
{
    int row = blockIdx.x;
    const float4* xr = (const float4*)(x + (size_t)row * H_);
    float4 v = xr[threadIdx.x];
    float s = v.x + v.y + v.z + v.w;
    float sq = v.x * v.x + v.y * v.y + v.z * v.z + v.w * v.w;
    #pragma unroll
    for (int o = 16; o; o >>= 1) {
        s  += __shfl_down_sync(0xffffffffu, s, o);
        sq += __shfl_down_sync(0xffffffffu, sq, o);
    }
    __shared__ float ss[8], ssq[8];
    int wrp = threadIdx.x >> 5, l = threadIdx.x & 31;
    if (l == 0) { ss[wrp] = s; ssq[wrp] = sq; }
    __syncthreads();
    if (wrp == 0) {
        s  = (l < 8) ? ss[l] : 0.f;
        sq = (l < 8) ? ssq[l] : 0.f;
        #pragma unroll
        for (int o = 4; o; o >>= 1) {
            s  += __shfl_down_sync(0xffu, s, o);
            sq += __shfl_down_sync(0xffu, sq, o);
        }
        if (l == 0) { ss[0] = s; ssq[0] = sq; }
    }
    __syncthreads();
    float mu = ss[0] * (1.f / H_);
    float var = ssq[0] * (1.f / H_) - mu * mu;
    float rs = rsqrtf(var + 1e-5f);
    float4 g = ((const float4*)ln_g)[threadIdx.x];
    float4 bb = ((const float4*)ln_b)[threadIdx.x];
    float o0 = (v.x - mu) * rs * g.x + bb.x;
    float o1 = (v.y - mu) * rs * g.y + bb.y;
    float o2 = (v.z - mu) * rs * g.z + bb.z;
    float o3 = (v.w - mu) * rs * g.w + bb.w;
    uint32_t h0, l0, h1, l1;
    split2(o0, o1, h0, l0);
    split2(o2, o3, h1, l1);
    int idx = row * (H_ / 4) + threadIdx.x;        // uint2 = 4 bf16
    ((uint2*)g_xh)[idx] = make_uint2(h0, h1);
    ((uint2*)g_xl)[idx] = make_uint2(l0, l1);
}

// ---------------- RoPE on base -> q, k (split bf16) --------------------------
__global__ __launch_bounds__(128) void rope_kernel(
    const float* __restrict__ gamma, const float* __restrict__ beta)
{
    int row = blockIdx.x;
    int t = threadIdx.x;
    __shared__ float pq[128], pk[128];
    float base = g_base[(size_t)row * S_ + t];
    pq[t] = base * gamma[t]       + beta[t];
    pk[t] = base * gamma[128 + t] + beta[128 + t];
    __syncthreads();
    int pos = row & (N_ - 1);
    float s, c, x1, x2, r1, r2;
    __nv_bfloat16 bh, bl;
    if (t < 64) {
        s = g_sin[pos * 64 + t]; c = g_cos[pos * 64 + t];
        x1 = pq[t]; x2 = pq[t + 64];
        r1 = x1 * c - x2 * s; r2 = x2 * c + x1 * s;
        size_t o = (size_t)row * S_ + t;
        bh = __float2bfloat16(r1); bl = __float2bfloat16(r1 - __bfloat162float(bh));
        g_qh[o] = bh; g_ql[o] = bl;
        bh = __float2bfloat16(r2); bl = __float2bfloat16(r2 - __bfloat162float(bh));
        g_qh[o + 64] = bh; g_ql[o + 64] = bl;
    } else {
        int d = t - 64;
        s = g_sin[pos * 64 + d]; c = g_cos[pos * 64 + d];
        x1 = pk[d]; x2 = pk[d + 64];
        r1 = x1 * c - x2 * s; r2 = x2 * c + x1 * s;
        size_t o = (size_t)row * S_ + d;
        bh = __float2bfloat16(r1); bl = __float2bfloat16(r1 - __bfloat162float(bh));
        g_kh[o] = bh; g_kl[o] = bl;
        bh = __float2bfloat16(r2); bl = __float2bfloat16(r2 - __bfloat162float(bh));
        g_kh[o + 64] = bh; g_kl[o + 64] = bl;
    }
}

// ---------------- launch -----------------------------------------------------
extern "C" void kernel_launch(void* const* d_in, const int* in_sizes, int n_in,
                              void* d_out, int out_size)
{
    const float* x     = (const float*)d_in[0];
    const float* mask  = (const float*)d_in[1];
    const float* gamma = (const float*)d_in[2];
    const float* beta  = (const float*)d_in[3];
    const float* w     = (const float*)d_in[4];
    const float* uv_w  = (const float*)d_in[7];
    const float* uv_b  = (const float*)d_in[8];
    const float* o_w   = (const float*)d_in[9];
    const float* o_b   = (const float*)d_in[10];
    const float* ln_g  = (const float*)d_in[11];
    const float* ln_b  = (const float*)d_in[12];
    float* out = (float*)d_out;

    cudaFuncSetAttribute(gau_gemm<1, 0, 32>, cudaFuncAttributeMaxDynamicSharedMemorySize, SMEMB);
    cudaFuncSetAttribute(gau_gemm<0, 1, 4>,  cudaFuncAttributeMaxDynamicSharedMemorySize, SMEMB);
    cudaFuncSetAttribute(gau_gemm<1, 2, 16>, cudaFuncAttributeMaxDynamicSharedMemorySize, SMEMB);
    cudaFuncSetAttribute(gau_gemm<1, 3, 64>, cudaFuncAttributeMaxDynamicSharedMemorySize, SMEMB);

    __nv_bfloat16 *p_xh, *p_xl, *p_wuh, *p_wul, *p_woh, *p_wol;
    __nv_bfloat16 *p_vh, *p_vl, *p_qh, *p_ql, *p_kh, *p_kl;
    __nv_bfloat16 *p_kerh, *p_kerl, *p_ahh, *p_all;
    cudaGetSymbolAddress((void**)&p_xh,  g_xh);  cudaGetSymbolAddress((void**)&p_xl,  g_xl);
    cudaGetSymbolAddress((void**)&p_wuh, g_wuh); cudaGetSymbolAddress((void**)&p_wul, g_wul);
    cudaGetSymbolAddress((void**)&p_woh, g_woh); cudaGetSymbolAddress((void**)&p_wol, g_wol);
    cudaGetSymbolAddress((void**)&p_vh,  g_vh);  cudaGetSymbolAddress((void**)&p_vl,  g_vl);
    cudaGetSymbolAddress((void**)&p_qh,  g_qh);  cudaGetSymbolAddress((void**)&p_ql,  g_ql);
    cudaGetSymbolAddress((void**)&p_kh,  g_kh);  cudaGetSymbolAddress((void**)&p_kl,  g_kl);
    cudaGetSymbolAddress((void**)&p_kerh,g_kerh);cudaGetSymbolAddress((void**)&p_kerl,g_kerl);
    cudaGetSymbolAddress((void**)&p_ahh, g_ah);  cudaGetSymbolAddress((void**)&p_all, g_al);

    sincos_kernel<<<128, 256>>>();
    split_kernel<<<(H_ * UVW / 2 + 255) / 256, 256>>>(uv_w, p_wuh, p_wul, H_ * UVW / 2);
    split_kernel<<<(E_ * H_ / 2 + 255) / 256, 256>>>(o_w, p_woh, p_wol, E_ * H_ / 2);
    ln_kernel<<<R_, 256>>>(x, ln_g, ln_b);

    // uv = silu(xn @ uv_w + uv_b)        [16384 x 4224 x 1024], B n-contig
    gau_gemm<1, 0, 32><<<dim3(UVW / 128, R_ / 128, 1), 512, SMEMB>>>(
        p_xh, p_xl, H_, 0LL, p_wuh, p_wul, UVW, 0LL, uv_b, nullptr, nullptr);

    rope_kernel<<<R_, 128>>>(gamma, beta);

    // kernel = relu(q@k^T/512 + bias + mask)^2   [512 x 512 x 128] x32, B k-contig
    gau_gemm<0, 1, 4><<<dim3(N_ / 128, N_ / 128, B_), 512, SMEMB>>>(
        p_qh, p_ql, S_, (long long)N_ * S_, p_kh, p_kl, S_, (long long)N_ * S_,
        w, mask, nullptr);

    // attn = u * (kernel @ v)            [512 x 2048 x 512] x32, B n-contig
    gau_gemm<1, 2, 16><<<dim3(E_ / 128, N_ / 128, B_), 512, SMEMB>>>(
        p_kerh, p_kerl, N_, (long long)N_ * N_, p_vh, p_vl, E_, (long long)N_ * E_,
        nullptr, nullptr, nullptr);

    // out = attn @ o_w + o_b + x         [16384 x 1024 x 2048], B n-contig
    gau_gemm<1, 3, 64><<<dim3(H_ / 128, R_ / 128, 1), 512, SMEMB>>>(
        p_ahh, p_all, E_, 0LL, p_woh, p_wol, H_, 0LL, o_b, x, out);
}

// round 15
// speedup vs baseline: 1.2344x; 1.0380x over previous
#include <cuda_runtime.h>
#include <cuda_bf16.h>
#include <cstdint>
#include <math.h>

// Problem constants
#define B_  32
#define N_  512
#define H_  1024
#define E_  2048
#define S_  128
#define R_  (B_ * N_)          // 16384 rows
#define UVW (2 * E_ + S_)      // 4224
#define MAXSEQ 512

// ---------------- scratch (device globals; no allocations allowed) ----------
// All GEMM operands are stored pre-split as bf16 (hi, lo) pairs.
__device__ __align__(16) __nv_bfloat16 g_xh[R_ * H_], g_xl[R_ * H_];       // LN out
__device__ __align__(16) __nv_bfloat16 g_wuh[H_ * UVW], g_wul[H_ * UVW];   // uv_w
__device__ __align__(16) __nv_bfloat16 g_woh[E_ * H_], g_wol[E_ * H_];     // o_w
__device__ __align__(16) float         g_u[R_ * E_];                       // gate (fp32)
__device__ __align__(16) __nv_bfloat16 g_vh[R_ * E_], g_vl[R_ * E_];       // v
__device__ __align__(16) float         g_base[R_ * S_];                    // pre-RoPE base
__device__ __align__(16) __nv_bfloat16 g_qh[R_ * S_], g_ql[R_ * S_];
__device__ __align__(16) __nv_bfloat16 g_kh[R_ * S_], g_kl[R_ * S_];
__device__ __align__(16) __nv_bfloat16 g_kerh[B_ * N_ * N_], g_kerl[B_ * N_ * N_];
__device__ __align__(16) __nv_bfloat16 g_ah[R_ * E_], g_al[R_ * E_];       // gated attn
__device__ float g_sin[N_ * 64];
__device__ float g_cos[N_ * 64];

// ---------------- smem stage layout (bytes), K-chunk = 32 --------------------
// NSTG = 2 (double buffer, 80 KB) so TWO CTAs co-reside per SM: each CTA's
// barriers/waits/epilogue overlap the other CTA's HMMA stream.
#define A_STRIDE 80            // 40 halfs per row (128 rows x 32 k), conflict-free
#define BSTRIDE_NC 272         // 136 halfs per k-row (32 k x 128 n), conflict-free
#define OFF_AL 10240
#define OFF_BH 20480
#define OFF_BL 30720
#define STAGE  40960
#define NSTG   2
#define SMEMB  (NSTG * STAGE)  // 80 KB -> 2 CTAs/SM

// ============================ PTX helpers ====================================
__device__ __forceinline__ uint32_t smem_u32(const void* p) {
    uint32_t a;
    asm("{ .reg .u64 t; cvta.to.shared.u64 t, %1; cvt.u32.u64 %0, t; }"
        : "=r"(a) : "l"(p));
    return a;
}
__device__ __forceinline__ void cpa16(uint32_t dst, const void* src) {
    asm volatile("cp.async.cg.shared.global [%0], [%1], 16;"
                 :: "r"(dst), "l"(src) : "memory");
}
#define CP_COMMIT() asm volatile("cp.async.commit_group;" ::: "memory")
template <int NW>
__device__ __forceinline__ void cp_wait() {
    asm volatile("cp.async.wait_group %0;" :: "n"(NW) : "memory");
}

__device__ __forceinline__ void ldm4(uint32_t r[4], uint32_t a) {
    asm volatile("ldmatrix.sync.aligned.m8n8.x4.shared.b16 {%0,%1,%2,%3}, [%4];"
        : "=r"(r[0]), "=r"(r[1]), "=r"(r[2]), "=r"(r[3]) : "r"(a));
}
__device__ __forceinline__ void ldm4t(uint32_t r[4], uint32_t a) {
    asm volatile("ldmatrix.sync.aligned.m8n8.x4.trans.shared.b16 {%0,%1,%2,%3}, [%4];"
        : "=r"(r[0]), "=r"(r[1]), "=r"(r[2]), "=r"(r[3]) : "r"(a));
}
__device__ __forceinline__ void mma16816(float d[4], const uint32_t a[4],
                                         const uint32_t b[2]) {
    asm volatile(
        "mma.sync.aligned.m16n8k16.row.col.f32.bf16.bf16.f32 "
        "{%0,%1,%2,%3}, {%4,%5,%6,%7}, {%8,%9}, {%0,%1,%2,%3};"
        : "+f"(d[0]), "+f"(d[1]), "+f"(d[2]), "+f"(d[3])
        : "r"(a[0]), "r"(a[1]), "r"(a[2]), "r"(a[3]), "r"(b[0]), "r"(b[1]));
}

// ---------------- bf16 hi/lo split -------------------------------------------
__device__ __forceinline__ void split2(float a, float b, uint32_t& hi, uint32_t& lo) {
    __nv_bfloat16 ah = __float2bfloat16(a), bh = __float2bfloat16(b);
    __nv_bfloat16 al = __float2bfloat16(a - __bfloat162float(ah));
    __nv_bfloat16 bl = __float2bfloat16(b - __bfloat162float(bh));
    __nv_bfloat162 h; h.x = ah; h.y = bh;
    __nv_bfloat162 l; l.x = al; l.y = bl;
    hi = *reinterpret_cast<uint32_t*>(&h);
    lo = *reinterpret_cast<uint32_t*>(&l);
}

// ---------------- generic bf16x3 mma.sync GEMM with fused epilogues ----------
// 128x128 CTA tile, 512 threads, 16 warps (4x4 grid) of 32x32 warp tiles.
// K-chunk 32, 2-stage cp.async pipeline, 2 CTAs/SM. NCH = K/32 compile-time.
// BNC: B operand is N-contiguous [K,N] (else K-contiguous [N,K])
// EPI: 0 = uv (bias+silu -> u | vh/vl | base), 1 = scores (-> kerh/kerl),
//      2 = attn (*u -> ah/al), 3 = out (+o_b + residual -> C)
template <int BNC, int EPI, int NCH>
__global__ __launch_bounds__(512, 2)
void gau_gemm(const __nv_bfloat16* __restrict__ Ah, const __nv_bfloat16* __restrict__ Al,
              int lda, long long sAz,
              const __nv_bfloat16* __restrict__ Bh, const __nv_bfloat16* __restrict__ Bl,
              int ldb, long long sBz,
              const float* __restrict__ e0, const float* __restrict__ e1,
              float* __restrict__ C)
{
    extern __shared__ char sm[];
    const int tid = threadIdx.x, wid = tid >> 5, lane = tid & 31;
    const int z = blockIdx.z;

    Ah += (size_t)z * sAz + (size_t)blockIdx.y * 128 * lda;
    Al += (size_t)z * sAz + (size_t)blockIdx.y * 128 * lda;
    if (BNC) { Bh += (size_t)z * sBz + blockIdx.x * 128;
               Bl += (size_t)z * sBz + blockIdx.x * 128; }
    else     { Bh += (size_t)z * sBz + (size_t)blockIdx.x * 128 * ldb;
               Bl += (size_t)z * sBz + (size_t)blockIdx.x * 128 * ldb; }

    const uint32_t sbase = smem_u32(sm);
    const int mb = (wid & 3) * 32;
    const int nb = (wid >> 2) * 32;

    // cp.async thread mappings (512 threads; one 16B granule per array)
    const int ar = tid >> 2, ag = tid & 3;     // kc: row 0..127, 16B granule
    const int bk = tid >> 4, bg = tid & 15;    // nc: k-row 0..31, 16B granule

    float acc[2][4][4];
    #pragma unroll
    for (int i = 0; i < 2; ++i)
        #pragma unroll
        for (int j = 0; j < 4; ++j)
            #pragma unroll
            for (int q = 0; q < 4; ++q) acc[i][j][q] = 0.f;

    auto issue = [&](int c) {
        uint32_t sb = sbase + (c & (NSTG - 1)) * STAGE;
        uint32_t da = sb + ar * A_STRIDE + ag * 16;
        cpa16(da,          Ah + (size_t)ar * lda + c * 32 + ag * 8);
        cpa16(da + OFF_AL, Al + (size_t)ar * lda + c * 32 + ag * 8);
        if (BNC) {
            uint32_t db = sb + OFF_BH + bk * BSTRIDE_NC + bg * 16;
            cpa16(db,                     Bh + (size_t)(c * 32 + bk) * ldb + bg * 8);
            cpa16(db + (OFF_BL - OFF_BH), Bl + (size_t)(c * 32 + bk) * ldb + bg * 8);
        } else {
            uint32_t db = sb + OFF_BH + ar * A_STRIDE + ag * 16;
            cpa16(db,                     Bh + (size_t)ar * ldb + c * 32 + ag * 8);
            cpa16(db + (OFF_BL - OFF_BH), Bl + (size_t)ar * ldb + c * 32 + ag * 8);
        }
        CP_COMMIT();
    };

    auto compute = [&](int c) {
        uint32_t sb = sbase + (c & (NSTG - 1)) * STAGE;
        #pragma unroll
        for (int ks = 0; ks < 2; ++ks) {
            uint32_t ah[2][4], al[2][4];
            #pragma unroll
            for (int mt = 0; mt < 2; ++mt) {
                uint32_t ad = sb + (mb + mt * 16 + (lane & 15)) * A_STRIDE
                            + ks * 32 + (lane >> 4) * 16;
                ldm4(ah[mt], ad);
                ldm4(al[mt], ad + OFF_AL);
            }
            uint32_t bh[4][2], bl[4][2];
            #pragma unroll
            for (int np = 0; np < 2; ++np) {     // each x4 covers two n8 groups
                uint32_t r[4];
                if (BNC) {
                    uint32_t bd = sb + OFF_BH
                                + (ks * 16 + (lane & 15)) * BSTRIDE_NC
                                + (nb + np * 16 + (lane >> 4) * 8) * 2;
                    ldm4t(r, bd);
                    bh[np*2][0]=r[0]; bh[np*2][1]=r[1]; bh[np*2+1][0]=r[2]; bh[np*2+1][1]=r[3];
                    ldm4t(r, bd + (OFF_BL - OFF_BH));
                    bl[np*2][0]=r[0]; bl[np*2][1]=r[1]; bl[np*2+1][0]=r[2]; bl[np*2+1][1]=r[3];
                } else {
                    uint32_t bd = sb + OFF_BH
                                + (nb + np * 16 + (lane >> 4) * 8 + (lane & 7)) * A_STRIDE
                                + ks * 32 + ((lane >> 3) & 1) * 16;
                    ldm4(r, bd);
                    bh[np*2][0]=r[0]; bh[np*2][1]=r[1]; bh[np*2+1][0]=r[2]; bh[np*2+1][1]=r[3];
                    ldm4(r, bd + (OFF_BL - OFF_BH));
                    bl[np*2][0]=r[0]; bl[np*2][1]=r[1]; bl[np*2+1][0]=r[2]; bl[np*2+1][1]=r[3];
                }
            }
            #pragma unroll
            for (int mt = 0; mt < 2; ++mt)
                #pragma unroll
                for (int nt = 0; nt < 4; ++nt) {
                    mma16816(acc[mt][nt], ah[mt], bh[nt]);
                    mma16816(acc[mt][nt], ah[mt], bl[nt]);
                    mma16816(acc[mt][nt], al[mt], bh[nt]);
                }
        }
    };

    issue(0);
    issue(1);

    // 2-stage pipeline: wait for group c, compute, then barrier before the
    // refill of the stage just consumed. The second barrier's cost is hidden
    // by the co-resident CTA on the same SM.
    #pragma unroll 4
    for (int c = 0; c < NCH; ++c) {
        if (c + 2 <= NCH) cp_wait<1>(); else cp_wait<0>();
        __syncthreads();                 // group c visible to all warps
        compute(c);
        if (c + 2 < NCH) {
            __syncthreads();             // all warps done reading stage c&1
            issue(c + 2);
        }
    }

    // ---------------- fused epilogue straight from fragments ----------------
    const int rbase = blockIdx.y * 128 + mb + (lane >> 2);
    const int cbase = blockIdx.x * 128 + nb + (lane & 3) * 2;
    const int xb = blockIdx.x;
    #pragma unroll
    for (int mt = 0; mt < 2; ++mt) {
        #pragma unroll
        for (int hf = 0; hf < 2; ++hf) {
            int r = rbase + mt * 16 + hf * 8;
            int grow = z * N_ + r;                  // global row (z=0 when unbatched)
            #pragma unroll
            for (int nt = 0; nt < 4; ++nt) {
                float v0 = acc[mt][nt][hf * 2 + 0];
                float v1 = acc[mt][nt][hf * 2 + 1];
                int cc = cbase + nt * 8;
                if (EPI == 0) {
                    v0 += e0[cc];     v1 += e0[cc + 1];
                    v0 = v0 / (1.f + expf(-v0));
                    v1 = v1 / (1.f + expf(-v1));
                    if (xb < 16) {
                        *(float2*)&g_u[(size_t)grow * E_ + cc] = make_float2(v0, v1);
                    } else if (xb < 32) {
                        uint32_t h, l; split2(v0, v1, h, l);
                        size_t idx = (size_t)grow * E_ + (cc - E_);
                        *(uint32_t*)&g_vh[idx] = h;
                        *(uint32_t*)&g_vl[idx] = l;
                    } else {
                        *(float2*)&g_base[(size_t)grow * S_ + (cc - 2 * E_)] =
                            make_float2(v0, v1);
                    }
                } else if (EPI == 1) {
                    float m0 = (1.f - e1[z * N_ + cc])     * (-1e12f);
                    float m1 = (1.f - e1[z * N_ + cc + 1]) * (-1e12f);
                    float s0 = v0 * (1.f / MAXSEQ) + e0[cc - r + (MAXSEQ - 1)]     + m0;
                    float s1 = v1 * (1.f / MAXSEQ) + e0[cc + 1 - r + (MAXSEQ - 1)] + m1;
                    s0 = fmaxf(s0, 0.f); s1 = fmaxf(s1, 0.f);
                    uint32_t h, l; split2(s0 * s0, s1 * s1, h, l);
                    size_t idx = ((size_t)z * N_ + r) * N_ + cc;
                    *(uint32_t*)&g_kerh[idx] = h;
                    *(uint32_t*)&g_kerl[idx] = l;
                } else if (EPI == 2) {
                    float2 u = *(const float2*)&g_u[(size_t)grow * E_ + cc];
                    uint32_t h, l; split2(v0 * u.x, v1 * u.y, h, l);
                    size_t idx = (size_t)grow * E_ + cc;
                    *(uint32_t*)&g_ah[idx] = h;
                    *(uint32_t*)&g_al[idx] = l;
                } else {
                    float2 xr = *(const float2*)&e1[(size_t)grow * H_ + cc];
                    *(float2*)&C[(size_t)grow * H_ + cc] =
                        make_float2(v0 + e0[cc] + xr.x, v1 + e0[cc + 1] + xr.y);
                }
            }
        }
    }
}

// ---------------- one-time fp32 -> bf16 hi/lo weight split -------------------
__global__ void split_kernel(const float* __restrict__ src,
                             __nv_bfloat16* __restrict__ h,
                             __nv_bfloat16* __restrict__ l, int n2) {
    int i = blockIdx.x * 256 + threadIdx.x;
    if (i >= n2) return;
    float2 v = ((const float2*)src)[i];
    uint32_t hi, lo; split2(v.x, v.y, hi, lo);
    ((uint32_t*)h)[i] = hi;
    ((uint32_t*)l)[i] = lo;
}

// ---------------- sin/cos table (replicates reference fp32 arithmetic) ------
__global__ void sincos_kernel() {
    int i = blockIdx.x * 256 + threadIdx.x;
    if (i >= N_ * 64) return;
    int d = i & 63;
    int pos = i >> 6;
    float invf = (float)pow(10000.0, (double)d * (1.0 / 64.0));
    float arg = (float)pos * invf;
    g_sin[i] = (float)sin((double)arg);
    g_cos[i] = (float)cos((double)arg);
}

// ---------------- LayerNorm -> split bf16 ------------------------------------
__global__ __launch_bounds__(256) void ln_kernel(
    const float* __restrict__ x, const float* __restrict__ ln_g,
    const float* __restrict__ ln_b)
{
    int row = blockIdx.x;
    const float4* xr = (const float4*)(x + (size_t)row * H_);
    float4 v = xr[threadIdx.x];
    float s = v.x + v.y + v.z + v.w;
    float sq = v.x * v.x + v.y * v.y + v.z * v.z + v.w * v.w;
    #pragma unroll
    for (int o = 16; o; o >>= 1) {
        s  += __shfl_down_sync(0xffffffffu, s, o);
        sq += __shfl_down_sync(0xffffffffu, sq, o);
    }
    __shared__ float ss[8], ssq[8];
    int wrp = threadIdx.x >> 5, l = threadIdx.x & 31;
    if (l == 0) { ss[wrp] = s; ssq[wrp] = sq; }
    __syncthreads();
    if (wrp == 0) {
        s  = (l < 8) ? ss[l] : 0.f;
        sq = (l < 8) ? ssq[l] : 0.f;
        #pragma unroll
        for (int o = 4; o; o >>= 1) {
            s  += __shfl_down_sync(0xffu, s, o);
            sq += __shfl_down_sync(0xffu, sq, o);
        }
        if (l == 0) { ss[0] = s; ssq[0] = sq; }
    }
    __syncthreads();
    float mu = ss[0] * (1.f / H_);
    float var = ssq[0] * (1.f / H_) - mu * mu;
    float rs = rsqrtf(var + 1e-5f);
    float4 g = ((const float4*)ln_g)[threadIdx.x];
    float4 bb = ((const float4*)ln_b)[threadIdx.x];
    float o0 = (v.x - mu) * rs * g.x + bb.x;
    float o1 = (v.y - mu) * rs * g.y + bb.y;
    float o2 = (v.z - mu) * rs * g.z + bb.z;
    float o3 = (v.w - mu) * rs * g.w + bb.w;
    uint32_t h0, l0, h1, l1;
    split2(o0, o1, h0, l0);
    split2(o2, o3, h1, l1);
    int idx = row * (H_ / 4) + threadIdx.x;        // uint2 = 4 bf16
    ((uint2*)g_xh)[idx] = make_uint2(h0, h1);
    ((uint2*)g_xl)[idx] = make_uint2(l0, l1);
}

// ---------------- RoPE on base -> q, k (split bf16) --------------------------
__global__ __launch_bounds__(128) void rope_kernel(
    const float* __restrict__ gamma, const float* __restrict__ beta)
{
    int row = blockIdx.x;
    int t = threadIdx.x;
    __shared__ float pq[128], pk[128];
    float base = g_base[(size_t)row * S_ + t];
    pq[t] = base * gamma[t]       + beta[t];
    pk[t] = base * gamma[128 + t] + beta[128 + t];
    __syncthreads();
    int pos = row & (N_ - 1);
    float s, c, x1, x2, r1, r2;
    __nv_bfloat16 bh, bl;
    if (t < 64) {
        s = g_sin[pos * 64 + t]; c = g_cos[pos * 64 + t];
        x1 = pq[t]; x2 = pq[t + 64];
        r1 = x1 * c - x2 * s; r2 = x2 * c + x1 * s;
        size_t o = (size_t)row * S_ + t;
        bh = __float2bfloat16(r1); bl = __float2bfloat16(r1 - __bfloat162float(bh));
        g_qh[o] = bh; g_ql[o] = bl;
        bh = __float2bfloat16(r2); bl = __float2bfloat16(r2 - __bfloat162float(bh));
        g_qh[o + 64] = bh; g_ql[o + 64] = bl;
    } else {
        int d = t - 64;
        s = g_sin[pos * 64 + d]; c = g_cos[pos * 64 + d];
        x1 = pk[d]; x2 = pk[d + 64];
        r1 = x1 * c - x2 * s; r2 = x2 * c + x1 * s;
        size_t o = (size_t)row * S_ + d;
        bh = __float2bfloat16(r1); bl = __float2bfloat16(r1 - __bfloat162float(bh));
        g_kh[o] = bh; g_kl[o] = bl;
        bh = __float2bfloat16(r2); bl = __float2bfloat16(r2 - __bfloat162float(bh));
        g_kh[o + 64] = bh; g_kl[o + 64] = bl;
    }
}

// ---------------- launch -----------------------------------------------------
extern "C" void kernel_launch(void* const* d_in, const int* in_sizes, int n_in,
                              void* d_out, int out_size)
{
    const float* x     = (const float*)d_in[0];
    const float* mask  = (const float*)d_in[1];
    const float* gamma = (const float*)d_in[2];
    const float* beta  = (const float*)d_in[3];
    const float* w     = (const float*)d_in[4];
    const float* uv_w  = (const float*)d_in[7];
    const float* uv_b  = (const float*)d_in[8];
    const float* o_w   = (const float*)d_in[9];
    const float* o_b   = (const float*)d_in[10];
    const float* ln_g  = (const float*)d_in[11];
    const float* ln_b  = (const float*)d_in[12];
    float* out = (float*)d_out;

    cudaFuncSetAttribute(gau_gemm<1, 0, 32>, cudaFuncAttributeMaxDynamicSharedMemorySize, SMEMB);
    cudaFuncSetAttribute(gau_gemm<0, 1, 4>,  cudaFuncAttributeMaxDynamicSharedMemorySize, SMEMB);
    cudaFuncSetAttribute(gau_gemm<1, 2, 16>, cudaFuncAttributeMaxDynamicSharedMemorySize, SMEMB);
    cudaFuncSetAttribute(gau_gemm<1, 3, 64>, cudaFuncAttributeMaxDynamicSharedMemorySize, SMEMB);

    __nv_bfloat16 *p_xh, *p_xl, *p_wuh, *p_wul, *p_woh, *p_wol;
    __nv_bfloat16 *p_vh, *p_vl, *p_qh, *p_ql, *p_kh, *p_kl;
    __nv_bfloat16 *p_kerh, *p_kerl, *p_ahh, *p_all;
    cudaGetSymbolAddress((void**)&p_xh,  g_xh);  cudaGetSymbolAddress((void**)&p_xl,  g_xl);
    cudaGetSymbolAddress((void**)&p_wuh, g_wuh); cudaGetSymbolAddress((void**)&p_wul, g_wul);
    cudaGetSymbolAddress((void**)&p_woh, g_woh); cudaGetSymbolAddress((void**)&p_wol, g_wol);
    cudaGetSymbolAddress((void**)&p_vh,  g_vh);  cudaGetSymbolAddress((void**)&p_vl,  g_vl);
    cudaGetSymbolAddress((void**)&p_qh,  g_qh);  cudaGetSymbolAddress((void**)&p_ql,  g_ql);
    cudaGetSymbolAddress((void**)&p_kh,  g_kh);  cudaGetSymbolAddress((void**)&p_kl,  g_kl);
    cudaGetSymbolAddress((void**)&p_kerh,g_kerh);cudaGetSymbolAddress((void**)&p_kerl,g_kerl);
    cudaGetSymbolAddress((void**)&p_ahh, g_ah);  cudaGetSymbolAddress((void**)&p_all, g_al);

    sincos_kernel<<<128, 256>>>();
    split_kernel<<<(H_ * UVW / 2 + 255) / 256, 256>>>(uv_w, p_wuh, p_wul, H_ * UVW / 2);
    split_kernel<<<(E_ * H_ / 2 + 255) / 256, 256>>>(o_w, p_woh, p_wol, E_ * H_ / 2);
    ln_kernel<<<R_, 256>>>(x, ln_g, ln_b);

    // uv = silu(xn @ uv_w + uv_b)        [16384 x 4224 x 1024], B n-contig
    gau_gemm<1, 0, 32><<<dim3(UVW / 128, R_ / 128, 1), 512, SMEMB>>>(
        p_xh, p_xl, H_, 0LL, p_wuh, p_wul, UVW, 0LL, uv_b, nullptr, nullptr);

    rope_kernel<<<R_, 128>>>(gamma, beta);

    // kernel = relu(q@k^T/512 + bias + mask)^2   [512 x 512 x 128] x32, B k-contig
    gau_gemm<0, 1, 4><<<dim3(N_ / 128, N_ / 128, B_), 512, SMEMB>>>(
        p_qh, p_ql, S_, (long long)N_ * S_, p_kh, p_kl, S_, (long long)N_ * S_,
        w, mask, nullptr);

    // attn = u * (kernel @ v)            [512 x 2048 x 512] x32, B n-contig
    gau_gemm<1, 2, 16><<<dim3(E_ / 128, N_ / 128, B_), 512, SMEMB>>>(
        p_kerh, p_kerl, N_, (long long)N_ * N_, p_vh, p_vl, E_, (long long)N_ * E_,
        nullptr, nullptr, nullptr);

    // out = attn @ o_w + o_b + x         [16384 x 1024 x 2048], B n-contig
    gau_gemm<1, 3, 64><<<dim3(H_ / 128, R_ / 128, 1), 512, SMEMB>>>(
        p_ahh, p_all, E_, 0LL, p_woh, p_wol, H_, 0LL, o_b, x, out);
}

// round 17
// speedup vs baseline: 1.3215x; 1.0706x over previous
#include <cuda_runtime.h>
#include <cuda_bf16.h>
#include <cstdint>
#include <math.h>

// Problem constants
#define B_  32
#define N_  512
#define H_  1024
#define E_  2048
#define S_  128
#define R_  (B_ * N_)          // 16384 rows
#define UVW (2 * E_ + S_)      // 4224
#define MAXSEQ 512

// ---------------- scratch (device globals; no allocations allowed) ----------
__device__ __align__(16) __nv_bfloat16 g_xh[R_ * H_], g_xl[R_ * H_];       // LN out
__device__ __align__(16) __nv_bfloat16 g_wuh[H_ * UVW], g_wul[H_ * UVW];   // uv_w
__device__ __align__(16) __nv_bfloat16 g_woh[E_ * H_], g_wol[E_ * H_];     // o_w
__device__ __align__(16) float         g_u[R_ * E_];                       // gate (fp32)
__device__ __align__(16) __nv_bfloat16 g_vh[R_ * E_], g_vl[R_ * E_];       // v
__device__ __align__(16) float         g_base[R_ * S_];                    // pre-RoPE base
__device__ __align__(16) __nv_bfloat16 g_qh[R_ * S_], g_ql[R_ * S_];
__device__ __align__(16) __nv_bfloat16 g_kh[R_ * S_], g_kl[R_ * S_];
__device__ __align__(16) __nv_bfloat16 g_kerh[B_ * N_ * N_], g_kerl[B_ * N_ * N_];
__device__ __align__(16) __nv_bfloat16 g_ah[R_ * E_], g_al[R_ * E_];       // gated attn
__device__ float g_sin[N_ * 64];
__device__ float g_cos[N_ * 64];

// ---------------- smem stage layouts (bytes), K-chunk = 32 -------------------
// A kc tile: 128 rows x 80B = 10240 (conflict-free ldmatrix).
// B nc tile: 32 k-rows x 272B = 8704 (compact).  B kc tile: 10240.
// BNC=1 (G1/G3/G4): compact stage 37888, NSTG=3  -> 113664 B/CTA, 2 CTAs/SM,
//   single barrier per chunk.
// BNC=0 (G2): stage 40960, NSTG=2 -> 81920 B/CTA, 2 CTAs/SM, R15 2-barrier loop.
#define A_STRIDE 80
#define BSTRIDE_NC 272
#define OFF_AL 10240
#define OFF_BH 20480
#define STAGE_NC 37888
#define STAGE_KC 40960
#define SMEM_NC (3 * STAGE_NC)   // 113664
#define SMEM_KC (2 * STAGE_KC)   // 81920

// ============================ PTX helpers ====================================
__device__ __forceinline__ uint32_t smem_u32(const void* p) {
    uint32_t a;
    asm("{ .reg .u64 t; cvta.to.shared.u64 t, %1; cvt.u32.u64 %0, t; }"
        : "=r"(a) : "l"(p));
    return a;
}
__device__ __forceinline__ void cpa16(uint32_t dst, const void* src) {
    asm volatile("cp.async.cg.shared.global [%0], [%1], 16;"
                 :: "r"(dst), "l"(src) : "memory");
}
#define CP_COMMIT() asm volatile("cp.async.commit_group;" ::: "memory")
template <int NW>
__device__ __forceinline__ void cp_wait() {
    asm volatile("cp.async.wait_group %0;" :: "n"(NW) : "memory");
}

__device__ __forceinline__ void ldm4(uint32_t r[4], uint32_t a) {
    asm volatile("ldmatrix.sync.aligned.m8n8.x4.shared.b16 {%0,%1,%2,%3}, [%4];"
        : "=r"(r[0]), "=r"(r[1]), "=r"(r[2]), "=r"(r[3]) : "r"(a));
}
__device__ __forceinline__ void ldm4t(uint32_t r[4], uint32_t a) {
    asm volatile("ldmatrix.sync.aligned.m8n8.x4.trans.shared.b16 {%0,%1,%2,%3}, [%4];"
        : "=r"(r[0]), "=r"(r[1]), "=r"(r[2]), "=r"(r[3]) : "r"(a));
}
__device__ __forceinline__ void mma16816(float d[4], const uint32_t a[4],
                                         const uint32_t b[2]) {
    asm volatile(
        "mma.sync.aligned.m16n8k16.row.col.f32.bf16.bf16.f32 "
        "{%0,%1,%2,%3}, {%4,%5,%6,%7}, {%8,%9}, {%0,%1,%2,%3};"
        : "+f"(d[0]), "+f"(d[1]), "+f"(d[2]), "+f"(d[3])
        : "r"(a[0]), "r"(a[1]), "r"(a[2]), "r"(a[3]), "r"(b[0]), "r"(b[1]));
}

// ---------------- bf16 hi/lo split -------------------------------------------
__device__ __forceinline__ void split2(float a, float b, uint32_t& hi, uint32_t& lo) {
    __nv_bfloat16 ah = __float2bfloat16(a), bh = __float2bfloat16(b);
    __nv_bfloat16 al = __float2bfloat16(a - __bfloat162float(ah));
    __nv_bfloat16 bl = __float2bfloat16(b - __bfloat162float(bh));
    __nv_bfloat162 h; h.x = ah; h.y = bh;
    __nv_bfloat162 l; l.x = al; l.y = bl;
    hi = *reinterpret_cast<uint32_t*>(&h);
    lo = *reinterpret_cast<uint32_t*>(&l);
}

// ---------------- generic bf16x3 mma.sync GEMM with fused epilogues ----------
// 128x128 CTA tile, 512 threads, 16 warps (4x4) of 32x32 warp tiles, 2 CTAs/SM.
// BNC: B operand is N-contiguous [K,N] (else K-contiguous [N,K])
// EPI: 0 = uv (bias+silu -> u | vh/vl | base), 1 = scores (-> kerh/kerl),
//      2 = attn (*u -> ah/al), 3 = out (+o_b + residual -> C)
template <int BNC, int EPI, int NCH>
__global__ __launch_bounds__(512, 2)
void gau_gemm(const __nv_bfloat16* __restrict__ Ah, const __nv_bfloat16* __restrict__ Al,
              int lda, long long sAz,
              const __nv_bfloat16* __restrict__ Bh, const __nv_bfloat16* __restrict__ Bl,
              int ldb, long long sBz,
              const float* __restrict__ e0, const float* __restrict__ e1,
              float* __restrict__ C)
{
    constexpr int STG   = BNC ? STAGE_NC : STAGE_KC;
    constexpr int NST   = BNC ? 3 : 2;
    constexpr int OFFBL = BNC ? 29184 : 30720;   // Bl region offset

    extern __shared__ char sm[];
    const int tid = threadIdx.x, wid = tid >> 5, lane = tid & 31;
    const int z = blockIdx.z;

    Ah += (size_t)z * sAz + (size_t)blockIdx.y * 128 * lda;
    Al += (size_t)z * sAz + (size_t)blockIdx.y * 128 * lda;
    if (BNC) { Bh += (size_t)z * sBz + blockIdx.x * 128;
               Bl += (size_t)z * sBz + blockIdx.x * 128; }
    else     { Bh += (size_t)z * sBz + (size_t)blockIdx.x * 128 * ldb;
               Bl += (size_t)z * sBz + (size_t)blockIdx.x * 128 * ldb; }

    const uint32_t sbase = smem_u32(sm);
    const int mb = (wid & 3) * 32;
    const int nb = (wid >> 2) * 32;

    // cp.async thread mappings (512 threads; one 16B granule per array)
    const int ar = tid >> 2, ag = tid & 3;     // kc: row 0..127, 16B granule
    const int bk = tid >> 4, bg = tid & 15;    // nc: k-row 0..31, 16B granule

    float acc[2][4][4];
    #pragma unroll
    for (int i = 0; i < 2; ++i)
        #pragma unroll
        for (int j = 0; j < 4; ++j)
            #pragma unroll
            for (int q = 0; q < 4; ++q) acc[i][j][q] = 0.f;

    auto issue = [&](int c) {
        uint32_t sb = sbase + (c % NST) * STG;
        uint32_t da = sb + ar * A_STRIDE + ag * 16;
        cpa16(da,          Ah + (size_t)ar * lda + c * 32 + ag * 8);
        cpa16(da + OFF_AL, Al + (size_t)ar * lda + c * 32 + ag * 8);
        if (BNC) {
            uint32_t db = sb + OFF_BH + bk * BSTRIDE_NC + bg * 16;
            cpa16(db,                    Bh + (size_t)(c * 32 + bk) * ldb + bg * 8);
            cpa16(db + (OFFBL - OFF_BH), Bl + (size_t)(c * 32 + bk) * ldb + bg * 8);
        } else {
            uint32_t db = sb + OFF_BH + ar * A_STRIDE + ag * 16;
            cpa16(db,                    Bh + (size_t)ar * ldb + c * 32 + ag * 8);
            cpa16(db + (OFFBL - OFF_BH), Bl + (size_t)ar * ldb + c * 32 + ag * 8);
        }
        CP_COMMIT();
    };

    auto compute = [&](int c) {
        uint32_t sb = sbase + (c % NST) * STG;
        #pragma unroll
        for (int ks = 0; ks < 2; ++ks) {
            uint32_t ah[2][4], al[2][4];
            #pragma unroll
            for (int mt = 0; mt < 2; ++mt) {
                uint32_t ad = sb + (mb + mt * 16 + (lane & 15)) * A_STRIDE
                            + ks * 32 + (lane >> 4) * 16;
                ldm4(ah[mt], ad);
                ldm4(al[mt], ad + OFF_AL);
            }
            uint32_t bh[4][2], bl[4][2];
            #pragma unroll
            for (int np = 0; np < 2; ++np) {     // each x4 covers two n8 groups
                uint32_t r[4];
                if (BNC) {
                    uint32_t bd = sb + OFF_BH
                                + (ks * 16 + (lane & 15)) * BSTRIDE_NC
                                + (nb + np * 16 + (lane >> 4) * 8) * 2;
                    ldm4t(r, bd);
                    bh[np*2][0]=r[0]; bh[np*2][1]=r[1]; bh[np*2+1][0]=r[2]; bh[np*2+1][1]=r[3];
                    ldm4t(r, bd + (OFFBL - OFF_BH));
                    bl[np*2][0]=r[0]; bl[np*2][1]=r[1]; bl[np*2+1][0]=r[2]; bl[np*2+1][1]=r[3];
                } else {
                    uint32_t bd = sb + OFF_BH
                                + (nb + np * 16 + (lane >> 4) * 8 + (lane & 7)) * A_STRIDE
                                + ks * 32 + ((lane >> 3) & 1) * 16;
                    ldm4(r, bd);
                    bh[np*2][0]=r[0]; bh[np*2][1]=r[1]; bh[np*2+1][0]=r[2]; bh[np*2+1][1]=r[3];
                    ldm4(r, bd + (OFFBL - OFF_BH));
                    bl[np*2][0]=r[0]; bl[np*2][1]=r[1]; bl[np*2+1][0]=r[2]; bl[np*2+1][1]=r[3];
                }
            }
            #pragma unroll
            for (int mt = 0; mt < 2; ++mt)
                #pragma unroll
                for (int nt = 0; nt < 4; ++nt) {
                    mma16816(acc[mt][nt], ah[mt], bh[nt]);
                    mma16816(acc[mt][nt], ah[mt], bl[nt]);
                    mma16816(acc[mt][nt], al[mt], bh[nt]);
                }
        }
    };

    if (BNC) {
        // 3-stage ring, ONE barrier per chunk.
        issue(0);
        issue(1);
        #pragma unroll 3
        for (int c = 0; c < NCH; ++c) {
            if (c + 1 < NCH) cp_wait<1>(); else cp_wait<0>();
            __syncthreads();             // group c visible; compute(c-1) done by all
            if (c + 2 < NCH) issue(c + 2);   // stage (c+2)%3 consumed at c-1: safe
            compute(c);
        }
    } else {
        // 2-stage ring (G2 only), two barriers per chunk (R15 scheme).
        issue(0);
        issue(1);
        #pragma unroll 4
        for (int c = 0; c < NCH; ++c) {
            if (c + 2 <= NCH) cp_wait<1>(); else cp_wait<0>();
            __syncthreads();
            compute(c);
            if (c + 2 < NCH) {
                __syncthreads();
                issue(c + 2);
            }
        }
    }

    // ---------------- fused epilogue straight from fragments ----------------
    const int rbase = blockIdx.y * 128 + mb + (lane >> 2);
    const int cbase = blockIdx.x * 128 + nb + (lane & 3) * 2;
    const int xb = blockIdx.x;
    #pragma unroll
    for (int mt = 0; mt < 2; ++mt) {
        #pragma unroll
        for (int hf = 0; hf < 2; ++hf) {
            int r = rbase + mt * 16 + hf * 8;
            int grow = z * N_ + r;                  // global row (z=0 when unbatched)
            #pragma unroll
            for (int nt = 0; nt < 4; ++nt) {
                float v0 = acc[mt][nt][hf * 2 + 0];
                float v1 = acc[mt][nt][hf * 2 + 1];
                int cc = cbase + nt * 8;
                if (EPI == 0) {
                    v0 += e0[cc];     v1 += e0[cc + 1];
                    v0 = v0 / (1.f + expf(-v0));
                    v1 = v1 / (1.f + expf(-v1));
                    if (xb < 16) {
                        *(float2*)&g_u[(size_t)grow * E_ + cc] = make_float2(v0, v1);
                    } else if (xb < 32) {
                        uint32_t h, l; split2(v0, v1, h, l);
                        size_t idx = (size_t)grow * E_ + (cc - E_);
                        *(uint32_t*)&g_vh[idx] = h;
                        *(uint32_t*)&g_vl[idx] = l;
                    } else {
                        *(float2*)&g_base[(size_t)grow * S_ + (cc - 2 * E_)] =
                            make_float2(v0, v1);
                    }
                } else if (EPI == 1) {
                    float m0 = (1.f - e1[z * N_ + cc])     * (-1e12f);
                    float m1 = (1.f - e1[z * N_ + cc + 1]) * (-1e12f);
                    float s0 = v0 * (1.f / MAXSEQ) + e0[cc - r + (MAXSEQ - 1)]     + m0;
                    float s1 = v1 * (1.f / MAXSEQ) + e0[cc + 1 - r + (MAXSEQ - 1)] + m1;
                    s0 = fmaxf(s0, 0.f); s1 = fmaxf(s1, 0.f);
                    uint32_t h, l; split2(s0 * s0, s1 * s1, h, l);
                    size_t idx = ((size_t)z * N_ + r) * N_ + cc;
                    *(uint32_t*)&g_kerh[idx] = h;
                    *(uint32_t*)&g_kerl[idx] = l;
                } else if (EPI == 2) {
                    float2 u = *(const float2*)&g_u[(size_t)grow * E_ + cc];
                    uint32_t h, l; split2(v0 * u.x, v1 * u.y, h, l);
                    size_t idx = (size_t)grow * E_ + cc;
                    *(uint32_t*)&g_ah[idx] = h;
                    *(uint32_t*)&g_al[idx] = l;
                } else {
                    float2 xr = *(const float2*)&e1[(size_t)grow * H_ + cc];
                    *(float2*)&C[(size_t)grow * H_ + cc] =
                        make_float2(v0 + e0[cc] + xr.x, v1 + e0[cc + 1] + xr.y);
                }
            }
        }
    }
}

// ---------------- one-time fp32 -> bf16 hi/lo weight split -------------------
__global__ void split_kernel(const float* __restrict__ src,
                             __nv_bfloat16* __restrict__ h,
                             __nv_bfloat16* __restrict__ l, int n2) {
    int i = blockIdx.x * 256 + threadIdx.x;
    if (i >= n2) return;
    float2 v = ((const float2*)src)[i];
    uint32_t hi, lo; split2(v.x, v.y, hi, lo);
    ((uint32_t*)h)[i] = hi;
    ((uint32_t*)l)[i] = lo;
}

// ---------------- sin/cos table (replicates reference fp32 arithmetic) ------
__global__ void sincos_kernel() {
    int i = blockIdx.x * 256 + threadIdx.x;
    if (i >= N_ * 64) return;
    int d = i & 63;
    int pos = i >> 6;
    float invf = (float)pow(10000.0, (double)d * (1.0 / 64.0));
    float arg = (float)pos * invf;
    g_sin[i] = (float)sin((double)arg);
    g_cos[i] = (float)cos((double)arg);
}

// ---------------- LayerNorm -> split bf16 ------------------------------------
__global__ __launch_bounds__(256) void ln_kernel(
    const float* __restrict__ x, const float* __restrict__ ln_g,
    const float* __restrict__ ln_b)
{
    int row = blockIdx.x;
    const float4* xr = (const float4*)(x + (size_t)row * H_);
    float4 v = xr[threadIdx.x];
    float s = v.x + v.y + v.z + v.w;
    float sq = v.x * v.x + v.y * v.y + v.z * v.z + v.w * v.w;
    #pragma unroll
    for (int o = 16; o; o >>= 1) {
        s  += __shfl_down_sync(0xffffffffu, s, o);
        sq += __shfl_down_sync(0xffffffffu, sq, o);
    }
    __shared__ float ss[8], ssq[8];
    int wrp = threadIdx.x >> 5, l = threadIdx.x & 31;
    if (l == 0) { ss[wrp] = s; ssq[wrp] = sq; }
    __syncthreads();
    if (wrp == 0) {
        s  = (l < 8) ? ss[l] : 0.f;
        sq = (l < 8) ? ssq[l] : 0.f;
        #pragma unroll
        for (int o = 4; o; o >>= 1) {
            s  += __shfl_down_sync(0xffu, s, o);
            sq += __shfl_down_sync(0xffu, sq, o);
        }
        if (l == 0) { ss[0] = s; ssq[0] = sq; }
    }
    __syncthreads();
    float mu = ss[0] * (1.f / H_);
    float var = ssq[0] * (1.f / H_) - mu * mu;
    float rs = rsqrtf(var + 1e-5f);
    float4 g = ((const float4*)ln_g)[threadIdx.x];
    float4 bb = ((const float4*)ln_b)[threadIdx.x];
    float o0 = (v.x - mu) * rs * g.x + bb.x;
    float o1 = (v.y - mu) * rs * g.y + bb.y;
    float o2 = (v.z - mu) * rs * g.z + bb.z;
    float o3 = (v.w - mu) * rs * g.w + bb.w;
    uint32_t h0, l0, h1, l1;
    split2(o0, o1, h0, l0);
    split2(o2, o3, h1, l1);
    int idx = row * (H_ / 4) + threadIdx.x;        // uint2 = 4 bf16
    ((uint2*)g_xh)[idx] = make_uint2(h0, h1);
    ((uint2*)g_xl)[idx] = make_uint2(l0, l1);
}

// ---------------- RoPE on base -> q, k (split bf16) --------------------------
__global__ __launch_bounds__(128) void rope_kernel(
    const float* __restrict__ gamma, const float* __restrict__ beta)
{
    int row = blockIdx.x;
    int t = threadIdx.x;
    __shared__ float pq[128], pk[128];
    float base = g_base[(size_t)row * S_ + t];
    pq[t] = base * gamma[t]       + beta[t];
    pk[t] = base * gamma[128 + t] + beta[128 + t];
    __syncthreads();
    int pos = row & (N_ - 1);
    float s, c, x1, x2, r1, r2;
    __nv_bfloat16 bh, bl;
    if (t < 64) {
        s = g_sin[pos * 64 + t]; c = g_cos[pos * 64 + t];
        x1 = pq[t]; x2 = pq[t + 64];
        r1 = x1 * c - x2 * s; r2 = x2 * c + x1 * s;
        size_t o = (size_t)row * S_ + t;
        bh = __float2bfloat16(r1); bl = __float2bfloat16(r1 - __bfloat162float(bh));
        g_qh[o] = bh; g_ql[o] = bl;
        bh = __float2bfloat16(r2); bl = __float2bfloat16(r2 - __bfloat162float(bh));
        g_qh[o + 64] = bh; g_ql[o + 64] = bl;
    } else {
        int d = t - 64;
        s = g_sin[pos * 64 + d]; c = g_cos[pos * 64 + d];
        x1 = pk[d]; x2 = pk[d + 64];
        r1 = x1 * c - x2 * s; r2 = x2 * c + x1 * s;
        size_t o = (size_t)row * S_ + d;
        bh = __float2bfloat16(r1); bl = __float2bfloat16(r1 - __bfloat162float(bh));
        g_kh[o] = bh; g_kl[o] = bl;
        bh = __float2bfloat16(r2); bl = __float2bfloat16(r2 - __bfloat162float(bh));
        g_kh[o + 64] = bh; g_kl[o + 64] = bl;
    }
}

// ---------------- launch -----------------------------------------------------
extern "C" void kernel_launch(void* const* d_in, const int* in_sizes, int n_in,
                              void* d_out, int out_size)
{
    const float* x     = (const float*)d_in[0];
    const float* mask  = (const float*)d_in[1];
    const float* gamma = (const float*)d_in[2];
    const float* beta  = (const float*)d_in[3];
    const float* w     = (const float*)d_in[4];
    const float* uv_w  = (const float*)d_in[7];
    const float* uv_b  = (const float*)d_in[8];
    const float* o_w   = (const float*)d_in[9];
    const float* o_b   = (const float*)d_in[10];
    const float* ln_g  = (const float*)d_in[11];
    const float* ln_b  = (const float*)d_in[12];
    float* out = (float*)d_out;

    cudaFuncSetAttribute(gau_gemm<1, 0, 32>, cudaFuncAttributeMaxDynamicSharedMemorySize, SMEM_NC);
    cudaFuncSetAttribute(gau_gemm<0, 1, 4>,  cudaFuncAttributeMaxDynamicSharedMemorySize, SMEM_KC);
    cudaFuncSetAttribute(gau_gemm<1, 2, 16>, cudaFuncAttributeMaxDynamicSharedMemorySize, SMEM_NC);
    cudaFuncSetAttribute(gau_gemm<1, 3, 64>, cudaFuncAttributeMaxDynamicSharedMemorySize, SMEM_NC);

    __nv_bfloat16 *p_xh, *p_xl, *p_wuh, *p_wul, *p_woh, *p_wol;
    __nv_bfloat16 *p_vh, *p_vl, *p_qh, *p_ql, *p_kh, *p_kl;
    __nv_bfloat16 *p_kerh, *p_kerl, *p_ahh, *p_all;
    cudaGetSymbolAddress((void**)&p_xh,  g_xh);  cudaGetSymbolAddress((void**)&p_xl,  g_xl);
    cudaGetSymbolAddress((void**)&p_wuh, g_wuh); cudaGetSymbolAddress((void**)&p_wul, g_wul);
    cudaGetSymbolAddress((void**)&p_woh, g_woh); cudaGetSymbolAddress((void**)&p_wol, g_wol);
    cudaGetSymbolAddress((void**)&p_vh,  g_vh);  cudaGetSymbolAddress((void**)&p_vl,  g_vl);
    cudaGetSymbolAddress((void**)&p_qh,  g_qh);  cudaGetSymbolAddress((void**)&p_ql,  g_ql);
    cudaGetSymbolAddress((void**)&p_kh,  g_kh);  cudaGetSymbolAddress((void**)&p_kl,  g_kl);
    cudaGetSymbolAddress((void**)&p_kerh,g_kerh);cudaGetSymbolAddress((void**)&p_kerl,g_kerl);
    cudaGetSymbolAddress((void**)&p_ahh, g_ah);  cudaGetSymbolAddress((void**)&p_all, g_al);

    sincos_kernel<<<128, 256>>>();
    split_kernel<<<(H_ * UVW / 2 + 255) / 256, 256>>>(uv_w, p_wuh, p_wul, H_ * UVW / 2);
    split_kernel<<<(E_ * H_ / 2 + 255) / 256, 256>>>(o_w, p_woh, p_wol, E_ * H_ / 2);
    ln_kernel<<<R_, 256>>>(x, ln_g, ln_b);

    // uv = silu(xn @ uv_w + uv_b)        [16384 x 4224 x 1024], B n-contig
    gau_gemm<1, 0, 32><<<dim3(UVW / 128, R_ / 128, 1), 512, SMEM_NC>>>(
        p_xh, p_xl, H_, 0LL, p_wuh, p_wul, UVW, 0LL, uv_b, nullptr, nullptr);

    rope_kernel<<<R_, 128>>>(gamma, beta);

    // kernel = relu(q@k^T/512 + bias + mask)^2   [512 x 512 x 128] x32, B k-contig
    gau_gemm<0, 1, 4><<<dim3(N_ / 128, N_ / 128, B_), 512, SMEM_KC>>>(
        p_qh, p_ql, S_, (long long)N_ * S_, p_kh, p_kl, S_, (long long)N_ * S_,
        w, mask, nullptr);

    // attn = u * (kernel @ v)            [512 x 2048 x 512] x32, B n-contig
    gau_gemm<1, 2, 16><<<dim3(E_ / 128, N_ / 128, B_), 512, SMEM_NC>>>(
        p_kerh, p_kerl, N_, (long long)N_ * N_, p_vh, p_vl, E_, (long long)N_ * E_,
        nullptr, nullptr, nullptr);

    // out = attn @ o_w + o_b + x         [16384 x 1024 x 2048], B n-contig
    gau_gemm<1, 3, 64><<<dim3(H_ / 128, R_ / 128, 1), 512, SMEM_NC>>>(
        p_ahh, p_all, E_, 0LL, p_woh, p_wol, H_, 0LL, o_b, x, out);
}